// round 2
// baseline (speedup 1.0000x reference)
#include <cuda_runtime.h>
#include <cstddef>

#define N_NODES 25000
#define N_EDGES 200000
#define NC 32

// ---------------- scratch (static device globals: allocation-free) ----------------
__device__ float g_hm[(size_t)N_NODES * 13 * NC];   // mixed features [n][comp(13)][c(32)]
__device__ float g_wt[3 * 32 * 32];                 // W transposed: wt[r][j][c] = W[r][c][j]
__device__ int   g_count[N_NODES];
__device__ int   g_off[N_NODES + 1];
__device__ int   g_cursor[N_NODES];
__device__ int   g_csr[N_EDGES];

// ---------------- init: zero histogram + transpose channel_weights ----------------
__global__ void init_kernel(const float* __restrict__ W) {
    int i = blockIdx.x * blockDim.x + threadIdx.x;
    if (i < N_NODES) g_count[i] = 0;
    if (i < 3 * 32 * 32) {
        int r = i >> 10, rem = i & 1023, j = rem >> 5, c = rem & 31;
        g_wt[i] = W[(r << 10) + (c << 5) + j];
    }
}

// ---------------- CSR build: histogram over send nodes ----------------
__global__ void hist_kernel(const int* __restrict__ eidx) {
    int e = blockIdx.x * blockDim.x + threadIdx.x;
    if (e < N_EDGES) atomicAdd(&g_count[eidx[e]], 1);   // row 0 = send
}

// ---------------- single-block exclusive scan over 25000 counts ----------------
__global__ void scan_kernel() {
    __shared__ int sh[1024];
    __shared__ int carry;
    int tid = threadIdx.x;
    if (tid == 0) carry = 0;
    __syncthreads();
    for (int base = 0; base < N_NODES; base += 1024) {
        int i = base + tid;
        int v = (i < N_NODES) ? g_count[i] : 0;
        sh[tid] = v;
        __syncthreads();
        for (int ofs = 1; ofs < 1024; ofs <<= 1) {
            int t = (tid >= ofs) ? sh[tid - ofs] : 0;
            __syncthreads();
            sh[tid] += t;
            __syncthreads();
        }
        int incl = sh[tid];
        int c_in = carry;
        if (i < N_NODES) {
            int x = c_in + incl - v;
            g_off[i] = x;
            g_cursor[i] = x;
        }
        __syncthreads();
        if (tid == 0) carry = c_in + sh[1023];
        __syncthreads();
    }
    if (tid == 0) g_off[N_NODES] = carry;
}

// ---------------- scatter edge ids into CSR slots ----------------
__global__ void scatter_kernel(const int* __restrict__ eidx) {
    int e = blockIdx.x * blockDim.x + threadIdx.x;
    if (e < N_EDGES) {
        int pos = atomicAdd(&g_cursor[eidx[e]], 1);
        g_csr[pos] = e;
    }
}

// ---------------- channel mixing: hm[n][comp][c] = sum_j W[r][c][j] h_r[n][j][d] ----------------
// one block per node; 13 warps = 13 output components; lane = output channel.
__global__ void mix_kernel(const float* __restrict__ h0, const float* __restrict__ h1,
                           const float* __restrict__ h2) {
    int n = blockIdx.x;
    int w = threadIdx.x >> 5;       // component 0..12
    int lane = threadIdx.x & 31;    // channel
    float hv;
    const float* wt;
    if (w == 0)      { hv = h0[n * 32 + lane];                 wt = g_wt;        }
    else if (w < 4)  { hv = h1[(n * 32 + lane) * 3 + (w - 1)]; wt = g_wt + 1024; }
    else             { hv = h2[(n * 32 + lane) * 9 + (w - 4)]; wt = g_wt + 2048; }
    float acc = 0.f;
#pragma unroll
    for (int j = 0; j < 32; j++) {
        float v = __shfl_sync(0xffffffffu, hv, j);   // h_r[n][j][d]
        acc = fmaf(v, wt[j * 32 + lane], acc);       // coalesced weight row
    }
    g_hm[((size_t)n * 13 + w) * 32 + lane] = acc;
}

// ---------------- main: warp per node, lane per channel, loop in-edges ----------------
__global__ void __launch_bounds__(256) node_kernel(
    const float* __restrict__ ea0, const float* __restrict__ ea1,
    const float* __restrict__ ea2, const int* __restrict__ eidx,
    float* __restrict__ out)
{
    int gw = (blockIdx.x * blockDim.x + threadIdx.x) >> 5;
    int lane = threadIdx.x & 31;
    if (gw >= N_NODES) return;
    int n = gw;
    int beg = g_off[n], end = g_off[n + 1];

    float acc[13];
#pragma unroll
    for (int k = 0; k < 13; k++) acc[k] = 0.f;

    for (int p = beg; p < end; p++) {
        int e = g_csr[p];
        int recv = eidx[N_EDGES + e];                // row 1 = recv
        const float* hm = g_hm + (size_t)recv * (13 * 32) + lane;

        float H0 = hm[0];
        float H1[3], H2[9];
#pragma unroll
        for (int k = 0; k < 3; k++) H1[k] = hm[(1 + k) * 32];
#pragma unroll
        for (int k = 0; k < 9; k++) H2[k] = hm[(4 + k) * 32];

        float a0 = ea0[e];                            // uniform per warp -> broadcast
        float a1[3], A2[9];
#pragma unroll
        for (int k = 0; k < 3; k++) a1[k] = ea1[e * 3 + k];
#pragma unroll
        for (int k = 0; k < 9; k++) A2[k] = ea2[e * 9 + k];

        float tA = A2[0] + A2[4] + A2[8];
        float tH = H2[0] + H2[4] + H2[8];
        float u = a0 + tA;        // a0 + tr(A2)
        float P = H0 + tH;        // H0 + tr(H2)

        float S[9], G[9];         // S = A2 + A2^T, G = H2 + H2^T (both symmetric)
#pragma unroll
        for (int i = 0; i < 3; i++)
#pragma unroll
            for (int j = 0; j < 3; j++) {
                S[i * 3 + j] = A2[i * 3 + j] + A2[j * 3 + i];
                G[i * 3 + j] = H2[i * 3 + j] + H2[j * 3 + i];
            }

        // rank-0 output
        float r0 = P * u;
#pragma unroll
        for (int k = 0; k < 3; k++) r0 = fmaf(H1[k], a1[k], r0);
#pragma unroll
        for (int k = 0; k < 9; k++) r0 = fmaf(H2[k], S[k], r0);
        acc[0] += r0;

        // rank-1 output
#pragma unroll
        for (int x = 0; x < 3; x++) {
            float r1 = fmaf(P, a1[x], u * H1[x]);
#pragma unroll
            for (int k = 0; k < 3; k++) r1 = fmaf(S[x * 3 + k], H1[k], r1);
#pragma unroll
            for (int k = 0; k < 3; k++) r1 = fmaf(G[x * 3 + k], a1[k], r1);
            acc[1 + x] += r1;
        }

        // rank-2 output
#pragma unroll
        for (int i = 0; i < 3; i++)
#pragma unroll
            for (int j = 0; j < 3; j++) {
                float r2 = fmaf(P, A2[i * 3 + j], fmaf(u, H2[i * 3 + j], H1[i] * a1[j]));
#pragma unroll
                for (int k = 0; k < 3; k++) r2 = fmaf(G[i * 3 + k], S[j * 3 + k], r2);
                acc[4 + i * 3 + j] += r2;
            }
    }

    // write outputs: [N,C] | [N,C,3] | [N,C,3,3] concatenated
    float* out0 = out;
    float* out1 = out + (size_t)N_NODES * NC;
    float* out2 = out + (size_t)N_NODES * NC * 4;
    out0[n * 32 + lane] = acc[0];
#pragma unroll
    for (int x = 0; x < 3; x++) out1[(n * 32 + lane) * 3 + x] = acc[1 + x];
#pragma unroll
    for (int k = 0; k < 9; k++) out2[(n * 32 + lane) * 9 + k] = acc[4 + k];
}

// ---------------- launch ----------------
extern "C" void kernel_launch(void* const* d_in, const int* in_sizes, int n_in,
                              void* d_out, int out_size) {
    const float* h0  = (const float*)d_in[0];
    const float* h1  = (const float*)d_in[1];
    const float* h2  = (const float*)d_in[2];
    // d_in[3] = rel_pos (unused by the math)
    const float* ea0 = (const float*)d_in[4];
    const float* ea1 = (const float*)d_in[5];
    const float* ea2 = (const float*)d_in[6];
    const float* W   = (const float*)d_in[7];
    const int*  eidx = (const int*)d_in[8];
    float* out = (float*)d_out;

    init_kernel<<<(N_NODES + 255) / 256, 256>>>(W);
    hist_kernel<<<(N_EDGES + 255) / 256, 256>>>(eidx);
    scan_kernel<<<1, 1024>>>();
    scatter_kernel<<<(N_EDGES + 255) / 256, 256>>>(eidx);
    mix_kernel<<<N_NODES, 13 * 32>>>(h0, h1, h2);
    node_kernel<<<(N_NODES * 32 + 255) / 256, 256>>>(ea0, ea1, ea2, eidx, out);
}

// round 3
// speedup vs baseline: 1.0528x; 1.0528x over previous
#include <cuda_runtime.h>
#include <cstddef>

#define N_NODES 25000
#define N_EDGES 200000
#define NC 32

// ---------------- scratch (static device globals: allocation-free) ----------------
__device__ float g_hm[(size_t)N_NODES * 13 * NC];   // mixed features [n][comp(13)][c(32)]
__device__ float g_wt[3 * 32 * 32];                 // W transposed: wt[r][j][c] = W[r][c][j]
__device__ int   g_count[N_NODES];
__device__ int   g_off[N_NODES + 1];
__device__ int   g_cursor[N_NODES];
__device__ int   g_csr[N_EDGES];
__device__ int   g_recv[N_EDGES];                   // recv node in CSR order (kills a dep level)

// ---------------- init: zero histogram + transpose channel_weights ----------------
__global__ void init_kernel(const float* __restrict__ W) {
    int i = blockIdx.x * blockDim.x + threadIdx.x;
    if (i < N_NODES) g_count[i] = 0;
    if (i < 3 * 32 * 32) {
        int r = i >> 10, rem = i & 1023, j = rem >> 5, c = rem & 31;
        g_wt[i] = W[(r << 10) + (c << 5) + j];
    }
}

// ---------------- CSR build: histogram over send nodes ----------------
__global__ void hist_kernel(const int* __restrict__ eidx) {
    int e = blockIdx.x * blockDim.x + threadIdx.x;
    if (e < N_EDGES) atomicAdd(&g_count[eidx[e]], 1);   // row 0 = send
}

// ---------------- one-pass exclusive scan: 1024 threads x 25-elem chunks ----------------
__global__ void scan_kernel() {
    __shared__ int warp_sums[32];
    const int CH = 25;                       // 1024*25 = 25600 >= N_NODES
    int tid = threadIdx.x;
    int lane = tid & 31, wid = tid >> 5;
    int base = tid * CH;

    int local[CH];
    int sum = 0;
#pragma unroll
    for (int k = 0; k < CH; k++) {
        int i = base + k;
        int v = (i < N_NODES) ? g_count[i] : 0;
        local[k] = v; sum += v;
    }
    // warp inclusive scan of per-thread sums
    int x = sum;
#pragma unroll
    for (int ofs = 1; ofs < 32; ofs <<= 1) {
        int t = __shfl_up_sync(0xffffffffu, x, ofs);
        if (lane >= ofs) x += t;
    }
    if (lane == 31) warp_sums[wid] = x;
    __syncthreads();
    if (wid == 0) {
        int w = warp_sums[lane];
#pragma unroll
        for (int ofs = 1; ofs < 32; ofs <<= 1) {
            int t = __shfl_up_sync(0xffffffffu, w, ofs);
            if (lane >= ofs) w += t;
        }
        warp_sums[lane] = w;
    }
    __syncthreads();
    int warp_excl = (wid == 0) ? 0 : warp_sums[wid - 1];
    int run = warp_excl + x - sum;           // exclusive prefix for this thread's chunk
#pragma unroll
    for (int k = 0; k < CH; k++) {
        int i = base + k;
        if (i < N_NODES) { g_off[i] = run; g_cursor[i] = run; }
        run += local[k];
    }
    if (tid == 1023) g_off[N_NODES] = run;   // grand total
}

// ---------------- scatter edge ids (+recv) into CSR slots ----------------
__global__ void scatter_kernel(const int* __restrict__ eidx) {
    int e = blockIdx.x * blockDim.x + threadIdx.x;
    if (e < N_EDGES) {
        int pos = atomicAdd(&g_cursor[eidx[e]], 1);
        g_csr[pos] = e;
        g_recv[pos] = eidx[N_EDGES + e];
    }
}

// ---------------- channel mixing: hm[n][comp][c] = sum_j W[r][c][j] h_r[n][j][d] ----------------
__global__ void mix_kernel(const float* __restrict__ h0, const float* __restrict__ h1,
                           const float* __restrict__ h2) {
    int n = blockIdx.x;
    int w = threadIdx.x >> 5;       // component 0..12
    int lane = threadIdx.x & 31;    // channel
    float hv;
    const float* wt;
    if (w == 0)      { hv = h0[n * 32 + lane];                 wt = g_wt;        }
    else if (w < 4)  { hv = h1[(n * 32 + lane) * 3 + (w - 1)]; wt = g_wt + 1024; }
    else             { hv = h2[(n * 32 + lane) * 9 + (w - 4)]; wt = g_wt + 2048; }
    float acc = 0.f;
#pragma unroll
    for (int j = 0; j < 32; j++) {
        float v = __shfl_sync(0xffffffffu, hv, j);
        acc = fmaf(v, wt[j * 32 + lane], acc);
    }
    g_hm[((size_t)n * 13 + w) * 32 + lane] = acc;
}

// ---------------- per-edge raw inputs + compute ----------------
struct EdgeIn {
    float H0, H1[3], H2[9];
    float a0, a1[3], A2[9];
};

__device__ __forceinline__ void load_edge(int p, int lane, EdgeIn& d,
                                          const float* __restrict__ ea0,
                                          const float* __restrict__ ea1,
                                          const float* __restrict__ ea2) {
    int e    = g_csr[p];
    int recv = g_recv[p];
    const float* hm = g_hm + (size_t)recv * (13 * 32) + lane;
    d.H0 = hm[0];
#pragma unroll
    for (int k = 0; k < 3; k++) d.H1[k] = hm[(1 + k) * 32];
#pragma unroll
    for (int k = 0; k < 9; k++) d.H2[k] = hm[(4 + k) * 32];
    d.a0 = ea0[e];
#pragma unroll
    for (int k = 0; k < 3; k++) d.a1[k] = ea1[e * 3 + k];
#pragma unroll
    for (int k = 0; k < 9; k++) d.A2[k] = ea2[e * 9 + k];
}

__device__ __forceinline__ void compute_edge(const EdgeIn& d, float acc[13]) {
    float tA = d.A2[0] + d.A2[4] + d.A2[8];
    float tH = d.H2[0] + d.H2[4] + d.H2[8];
    float u = d.a0 + tA;
    float P = d.H0 + tH;

    float S[9], G[9];
#pragma unroll
    for (int i = 0; i < 3; i++)
#pragma unroll
        for (int j = 0; j < 3; j++) {
            S[i * 3 + j] = d.A2[i * 3 + j] + d.A2[j * 3 + i];
            G[i * 3 + j] = d.H2[i * 3 + j] + d.H2[j * 3 + i];
        }

    float r0 = P * u;
#pragma unroll
    for (int k = 0; k < 3; k++) r0 = fmaf(d.H1[k], d.a1[k], r0);
#pragma unroll
    for (int k = 0; k < 9; k++) r0 = fmaf(d.H2[k], S[k], r0);
    acc[0] += r0;

#pragma unroll
    for (int x = 0; x < 3; x++) {
        float r1 = fmaf(P, d.a1[x], u * d.H1[x]);
#pragma unroll
        for (int k = 0; k < 3; k++) r1 = fmaf(S[x * 3 + k], d.H1[k], r1);
#pragma unroll
        for (int k = 0; k < 3; k++) r1 = fmaf(G[x * 3 + k], d.a1[k], r1);
        acc[1 + x] += r1;
    }

#pragma unroll
    for (int i = 0; i < 3; i++)
#pragma unroll
        for (int j = 0; j < 3; j++) {
            float r2 = fmaf(P, d.A2[i * 3 + j], fmaf(u, d.H2[i * 3 + j], d.H1[i] * d.a1[j]));
#pragma unroll
            for (int k = 0; k < 3; k++) r2 = fmaf(G[i * 3 + k], S[j * 3 + k], r2);
            acc[4 + i * 3 + j] += r2;
        }
}

// ---------------- main: warp per node, lane per channel, 2x-unrolled edge loop ----------------
__global__ void __launch_bounds__(256) node_kernel(
    const float* __restrict__ ea0, const float* __restrict__ ea1,
    const float* __restrict__ ea2, float* __restrict__ out)
{
    int gw = (blockIdx.x * blockDim.x + threadIdx.x) >> 5;
    int lane = threadIdx.x & 31;
    if (gw >= N_NODES) return;
    int n = gw;
    int beg = g_off[n], end = g_off[n + 1];

    float acc[13];
#pragma unroll
    for (int k = 0; k < 13; k++) acc[k] = 0.f;

    int p = beg;
    for (; p + 1 < end; p += 2) {
        EdgeIn dA, dB;
        load_edge(p,     lane, dA, ea0, ea1, ea2);   // both edges' loads issued
        load_edge(p + 1, lane, dB, ea0, ea1, ea2);   // before any compute -> 2x MLP
        compute_edge(dA, acc);
        compute_edge(dB, acc);
    }
    if (p < end) {
        EdgeIn dA;
        load_edge(p, lane, dA, ea0, ea1, ea2);
        compute_edge(dA, acc);
    }

    // write outputs: [N,C] | [N,C,3] | [N,C,3,3] concatenated
    float* out0 = out;
    float* out1 = out + (size_t)N_NODES * NC;
    float* out2 = out + (size_t)N_NODES * NC * 4;
    out0[n * 32 + lane] = acc[0];
#pragma unroll
    for (int x = 0; x < 3; x++) out1[(n * 32 + lane) * 3 + x] = acc[1 + x];
#pragma unroll
    for (int k = 0; k < 9; k++) out2[(n * 32 + lane) * 9 + k] = acc[4 + k];
}

// ---------------- launch ----------------
extern "C" void kernel_launch(void* const* d_in, const int* in_sizes, int n_in,
                              void* d_out, int out_size) {
    const float* h0  = (const float*)d_in[0];
    const float* h1  = (const float*)d_in[1];
    const float* h2  = (const float*)d_in[2];
    // d_in[3] = rel_pos (unused by the math)
    const float* ea0 = (const float*)d_in[4];
    const float* ea1 = (const float*)d_in[5];
    const float* ea2 = (const float*)d_in[6];
    const float* W   = (const float*)d_in[7];
    const int*  eidx = (const int*)d_in[8];
    float* out = (float*)d_out;

    init_kernel<<<(N_NODES + 255) / 256, 256>>>(W);
    hist_kernel<<<(N_EDGES + 255) / 256, 256>>>(eidx);
    scan_kernel<<<1, 1024>>>();
    scatter_kernel<<<(N_EDGES + 255) / 256, 256>>>(eidx);
    mix_kernel<<<N_NODES, 13 * 32>>>(h0, h1, h2);
    node_kernel<<<(N_NODES * 32 + 255) / 256, 256>>>(ea0, ea1, ea2, out);
}

// round 4
// speedup vs baseline: 1.0871x; 1.0326x over previous
#include <cuda_runtime.h>
#include <cstddef>

#define N_NODES 25000
#define N_EDGES 200000
#define NC 32

#define HIST_BLOCKS 481          // 481*416 >= 200000
#define MIX_NB 25                // nodes per mix block
#define MIX_BLOCKS 1000          // 1000*25 = 25000
#define FUSED_THREADS 416        // 13 warps

// ---------------- scratch (static device globals: allocation-free) ----------------
__device__ float g_hm[(size_t)N_NODES * 13 * NC];   // mixed features [n][comp(13)][c(32)]
__device__ int   g_count[N_NODES];                  // zero at load; re-zeroed by node_kernel
__device__ int   g_off[N_NODES + 1];
__device__ int   g_cursor[N_NODES];
__device__ float g_rec[(size_t)N_EDGES * 16];       // packed per-edge record in CSR order

// ---------------- K1: fused histogram (blocks 0..480) + channel mix (rest) ----------------
__global__ void __launch_bounds__(FUSED_THREADS) hist_mix_kernel(
    const int* __restrict__ eidx,
    const float* __restrict__ h0, const float* __restrict__ h1,
    const float* __restrict__ h2, const float* __restrict__ W)
{
    if (blockIdx.x < HIST_BLOCKS) {
        int e = blockIdx.x * FUSED_THREADS + threadIdx.x;
        if (e < N_EDGES) atomicAdd(&g_count[eidx[e]], 1);   // row 0 = send
        return;
    }

    // ---- mix part: hm[n][w][c] = sum_j W[r][c][j] * h_r[n][j][d] ----
    __shared__ float w_s[3 * 32 * 33];     // padded: bank = (c + j) % 32, conflict-free
    int tid = threadIdx.x;
    for (int idx = tid; idx < 3 * 32 * 32; idx += FUSED_THREADS) {
        int r = idx >> 10, rem = idx & 1023, c = rem >> 5, j = rem & 31;
        w_s[(r * 32 + c) * 33 + j] = W[idx];
    }
    __syncthreads();

    int w = tid >> 5;          // component 0..12
    int lane = tid & 31;       // output channel
    int r = (w == 0) ? 0 : (w < 4 ? 1 : 2);
    int d = (w == 0) ? 0 : (w < 4 ? (w - 1) : (w - 4));

    float wreg[32];
    {
        const float* base = w_s + (r * 32 + lane) * 33;
#pragma unroll
        for (int j = 0; j < 32; j++) wreg[j] = base[j];
    }

    int nb = (blockIdx.x - HIST_BLOCKS) * MIX_NB;
#pragma unroll 1
    for (int n = nb; n < nb + MIX_NB; n++) {
        float hv;
        if (w == 0)      hv = h0[n * 32 + lane];
        else if (w < 4)  hv = h1[(n * 32 + lane) * 3 + d];
        else             hv = h2[(n * 32 + lane) * 9 + d];
        float a0 = 0.f, a1 = 0.f, a2 = 0.f, a3 = 0.f;
#pragma unroll
        for (int j = 0; j < 32; j += 4) {
            a0 = fmaf(__shfl_sync(0xffffffffu, hv, j + 0), wreg[j + 0], a0);
            a1 = fmaf(__shfl_sync(0xffffffffu, hv, j + 1), wreg[j + 1], a1);
            a2 = fmaf(__shfl_sync(0xffffffffu, hv, j + 2), wreg[j + 2], a2);
            a3 = fmaf(__shfl_sync(0xffffffffu, hv, j + 3), wreg[j + 3], a3);
        }
        g_hm[((size_t)n * 13 + w) * 32 + lane] = (a0 + a1) + (a2 + a3);
    }
}

// ---------------- K2: one-pass exclusive scan (1024 threads x 25-elem chunks) ----------------
__global__ void scan_kernel() {
    __shared__ int warp_sums[32];
    const int CH = 25;                       // 1024*25 = 25600 >= N_NODES
    int tid = threadIdx.x;
    int lane = tid & 31, wid = tid >> 5;
    int base = tid * CH;

    int local[CH];
    int sum = 0;
#pragma unroll
    for (int k = 0; k < CH; k++) {
        int i = base + k;
        int v = (i < N_NODES) ? g_count[i] : 0;
        local[k] = v; sum += v;
    }
    int x = sum;
#pragma unroll
    for (int ofs = 1; ofs < 32; ofs <<= 1) {
        int t = __shfl_up_sync(0xffffffffu, x, ofs);
        if (lane >= ofs) x += t;
    }
    if (lane == 31) warp_sums[wid] = x;
    __syncthreads();
    if (wid == 0) {
        int wv = warp_sums[lane];
#pragma unroll
        for (int ofs = 1; ofs < 32; ofs <<= 1) {
            int t = __shfl_up_sync(0xffffffffu, wv, ofs);
            if (lane >= ofs) wv += t;
        }
        warp_sums[lane] = wv;
    }
    __syncthreads();
    int warp_excl = (wid == 0) ? 0 : warp_sums[wid - 1];
    int run = warp_excl + x - sum;
#pragma unroll
    for (int k = 0; k < CH; k++) {
        int i = base + k;
        if (i < N_NODES) { g_off[i] = run; g_cursor[i] = run; }
        run += local[k];
    }
    if (tid == 1023) g_off[N_NODES] = run;
}

// ---------------- K3: scatter packed edge records into CSR slots ----------------
__global__ void scatter_pack_kernel(
    const int* __restrict__ eidx, const float* __restrict__ ea0,
    const float* __restrict__ ea1, const float* __restrict__ ea2)
{
    int e = blockIdx.x * blockDim.x + threadIdx.x;
    if (e >= N_EDGES) return;
    int send = eidx[e];
    int recv = eidx[N_EDGES + e];
    float a0 = ea0[e];
    float a1x = ea1[e * 3 + 0], a1y = ea1[e * 3 + 1], a1z = ea1[e * 3 + 2];
    float A2[9];
#pragma unroll
    for (int k = 0; k < 9; k++) A2[k] = ea2[e * 9 + k];
    float u = a0 + A2[0] + A2[4] + A2[8];

    int pos = atomicAdd(&g_cursor[send], 1);
    float4* r = (float4*)(g_rec + (size_t)pos * 16);
    r[0] = make_float4(u, a1x, a1y, a1z);
    r[1] = make_float4(A2[0], A2[1], A2[2], A2[3]);
    r[2] = make_float4(A2[4], A2[5], A2[6], A2[7]);
    r[3] = make_float4(A2[8], __int_as_float(recv), 0.f, 0.f);
}

// ---------------- per-edge compute ----------------
struct EdgeIn {
    float H0, H1[3], H2[9];
    float u, a1[3], A2[9];
    int recv;
};

__device__ __forceinline__ void load_edge(int p, int lane, EdgeIn& d) {
    const float4* rec = (const float4*)(g_rec + (size_t)p * 16);
    float4 ra = rec[0], rb = rec[1], rc4 = rec[2], rd = rec[3];   // broadcast loads
    d.u = ra.x; d.a1[0] = ra.y; d.a1[1] = ra.z; d.a1[2] = ra.w;
    d.A2[0] = rb.x; d.A2[1] = rb.y; d.A2[2] = rb.z; d.A2[3] = rb.w;
    d.A2[4] = rc4.x; d.A2[5] = rc4.y; d.A2[6] = rc4.z; d.A2[7] = rc4.w;
    d.A2[8] = rd.x; d.recv = __float_as_int(rd.y);
    const float* hm = g_hm + (size_t)d.recv * (13 * 32) + lane;
    d.H0 = hm[0];
#pragma unroll
    for (int k = 0; k < 3; k++) d.H1[k] = hm[(1 + k) * 32];
#pragma unroll
    for (int k = 0; k < 9; k++) d.H2[k] = hm[(4 + k) * 32];
}

__device__ __forceinline__ void compute_edge(const EdgeIn& d, float acc[13]) {
    float tH = d.H2[0] + d.H2[4] + d.H2[8];
    float u = d.u;
    float P = d.H0 + tH;

    float S[9], G[9];
#pragma unroll
    for (int i = 0; i < 3; i++)
#pragma unroll
        for (int j = 0; j < 3; j++) {
            S[i * 3 + j] = d.A2[i * 3 + j] + d.A2[j * 3 + i];
            G[i * 3 + j] = d.H2[i * 3 + j] + d.H2[j * 3 + i];
        }

    float r0 = P * u;
#pragma unroll
    for (int k = 0; k < 3; k++) r0 = fmaf(d.H1[k], d.a1[k], r0);
#pragma unroll
    for (int k = 0; k < 9; k++) r0 = fmaf(d.H2[k], S[k], r0);
    acc[0] += r0;

#pragma unroll
    for (int x = 0; x < 3; x++) {
        float r1 = fmaf(P, d.a1[x], u * d.H1[x]);
#pragma unroll
        for (int k = 0; k < 3; k++) r1 = fmaf(S[x * 3 + k], d.H1[k], r1);
#pragma unroll
        for (int k = 0; k < 3; k++) r1 = fmaf(G[x * 3 + k], d.a1[k], r1);
        acc[1 + x] += r1;
    }

#pragma unroll
    for (int i = 0; i < 3; i++)
#pragma unroll
        for (int j = 0; j < 3; j++) {
            float r2 = fmaf(P, d.A2[i * 3 + j], fmaf(u, d.H2[i * 3 + j], d.H1[i] * d.a1[j]));
#pragma unroll
            for (int k = 0; k < 3; k++) r2 = fmaf(G[i * 3 + k], S[j * 3 + k], r2);
            acc[4 + i * 3 + j] += r2;
        }
}

// ---------------- K4: warp per node; also re-zeroes g_count for the next call ----------------
__global__ void __launch_bounds__(256) node_kernel(float* __restrict__ out) {
    int gid = blockIdx.x * blockDim.x + threadIdx.x;
    if (gid < N_NODES) g_count[gid] = 0;     // prep for next replay (safe: hist is next launch)

    int gw = gid >> 5;
    int lane = threadIdx.x & 31;
    if (gw >= N_NODES) return;
    int n = gw;
    int beg = g_off[n], end = g_off[n + 1];

    float acc[13];
#pragma unroll
    for (int k = 0; k < 13; k++) acc[k] = 0.f;

    int p = beg;
    for (; p + 1 < end; p += 2) {
        EdgeIn dA, dB;
        load_edge(p, lane, dA);       // all loads for both edges issued
        load_edge(p + 1, lane, dB);   // before any compute -> 2x MLP
        compute_edge(dA, acc);
        compute_edge(dB, acc);
    }
    if (p < end) {
        EdgeIn dA;
        load_edge(p, lane, dA);
        compute_edge(dA, acc);
    }

    float* out0 = out;
    float* out1 = out + (size_t)N_NODES * NC;
    float* out2 = out + (size_t)N_NODES * NC * 4;
    out0[n * 32 + lane] = acc[0];
#pragma unroll
    for (int x = 0; x < 3; x++) out1[(n * 32 + lane) * 3 + x] = acc[1 + x];
#pragma unroll
    for (int k = 0; k < 9; k++) out2[(n * 32 + lane) * 9 + k] = acc[4 + k];
}

// ---------------- launch ----------------
extern "C" void kernel_launch(void* const* d_in, const int* in_sizes, int n_in,
                              void* d_out, int out_size) {
    const float* h0  = (const float*)d_in[0];
    const float* h1  = (const float*)d_in[1];
    const float* h2  = (const float*)d_in[2];
    // d_in[3] = rel_pos (unused by the math)
    const float* ea0 = (const float*)d_in[4];
    const float* ea1 = (const float*)d_in[5];
    const float* ea2 = (const float*)d_in[6];
    const float* W   = (const float*)d_in[7];
    const int*  eidx = (const int*)d_in[8];
    float* out = (float*)d_out;

    hist_mix_kernel<<<HIST_BLOCKS + MIX_BLOCKS, FUSED_THREADS>>>(eidx, h0, h1, h2, W);
    scan_kernel<<<1, 1024>>>();
    scatter_pack_kernel<<<(N_EDGES + 255) / 256, 256>>>(eidx, ea0, ea1, ea2);
    node_kernel<<<(N_NODES * 32 + 255) / 256, 256>>>(out);
}